// round 5
// baseline (speedup 1.0000x reference)
#include <cuda_runtime.h>
#include <cuda_bf16.h>
#include <math.h>
#include <stdint.h>

#define B_   512
#define T_   60
#define V_   50000
#define E_   300
#define EP_  320          // E padded to multiple of 64
#define H_   512
#define M_   256
#define R_   1024         // 2*B rows (both sequences batched)
#define N4H  2048         // 4*H (gate-interleaved permuted layout)
#define KH_  512
#define NCTA 128          // persistent lstm grid size

// Feature gate: tcgen05 only exists in the arch-specific (sm_103a/sm_100a)
// compilation passes. The plain compute_103/sm_103 pass gets an FFMA fallback.
#if defined(__CUDA_ARCH__) && (defined(__CUDA_ARCH_FEAT_SM103_ALL) || \
                               defined(__CUDA_ARCH_FEAT_SM100_ALL) || \
                               (defined(__CUDA_ARCH_SPECIFIC__) && (__CUDA_ARCH_SPECIFIC__ >= 1000)))
#define HAS_TC 1
#else
#define HAS_TC 0
#endif

// ---------------------------------------------------------------------------
// Device scratch (static allocations — allowed)
// ---------------------------------------------------------------------------
__device__ __align__(16) float g_XZ[(size_t)T_ * R_ * N4H];   // x-proj + bias, permuted cols
__device__ __align__(16) float g_H[R_ * H_];                  // final h (for head)
__device__ __align__(16) __nv_bfloat16 g_Hhi[2][R_ * H_];     // ping-pong H splits
__device__ __align__(16) __nv_bfloat16 g_Hlo[2][R_ * H_];
__device__ __align__(16) __nv_bfloat16 g_Ehi[(size_t)V_ * EP_];
__device__ __align__(16) __nv_bfloat16 g_Elo[(size_t)V_ * EP_];
__device__ __align__(16) __nv_bfloat16 g_WxThi[N4H * EP_];    // [n_perm][k], K-major
__device__ __align__(16) __nv_bfloat16 g_WxTlo[N4H * EP_];
__device__ __align__(16) __nv_bfloat16 g_WhThi[N4H * KH_];
__device__ __align__(16) __nv_bfloat16 g_WhTlo[N4H * KH_];
__device__ int g_flags[NCTA];                                  // gmem barrier flags

__device__ __forceinline__ float sigmoidf_(float x) { return 1.f / (1.f + expf(-x)); }

// SMEM layouts (both kernels use 132096 bytes)
#define SMEM_BYTES  (1024 + 2 * 65536)
// lstm: two buffers of 4 tiles [Ah,Al,Bh,Bl]
#define SM_BUF(b)   (1024 + (b) * 65536)
// xproj: A buffers (2 x [Ah,Al]) then B buffers (2 x [Bh,Bl])
#define XA_BUF(b)   (1024 + (b) * 32768)
#define XB_BUF(b)   (1024 + 65536 + (b) * 32768)

#if HAS_TC
// ---------------------------------------------------------------------------
// PTX helpers (sm_103a only)
// ---------------------------------------------------------------------------
__device__ __forceinline__ uint32_t smem_u32(const void* p) {
    uint32_t a;
    asm("{ .reg .u64 t; cvta.to.shared.u64 t, %1; cvt.u32.u64 %0, t; }" : "=r"(a) : "l"(p));
    return a;
}
__device__ __forceinline__ uint32_t elect_one() {
    uint32_t p;
    asm volatile("{ .reg .pred p; elect.sync _|p, 0xFFFFFFFF; selp.b32 %0, 1, 0, p; }" : "=r"(p));
    return p;
}

// idesc: c=F32, a=BF16 K-major, b=BF16 K-major, M=128, N=128
#define IDESC_128x128 0x8200490u
// SW128 desc base: layout=2, version=1, SBO=64, LBO=1
#define DESC_BASE ((2ull << 61) | (1ull << 46) | (64ull << 32) | (1ull << 16))

__device__ __forceinline__ uint64_t mk_desc(uint32_t smem_addr) {
    return DESC_BASE | ((uint64_t)(smem_addr >> 4) & 0x3FFF);
}

__device__ __forceinline__ void mma_f16_ss(uint32_t d, uint64_t ad, uint64_t bd, uint32_t acc) {
    asm volatile(
        "{\n\t.reg .pred p;\n\tsetp.ne.u32 p, %5, 0;\n\t"
        "tcgen05.mma.cta_group::1.kind::f16 [%0], %1, %2, %3, {%4, %4, %4, %4}, p;\n\t}\n"
        :: "r"(d), "l"(ad), "l"(bd), "r"(IDESC_128x128), "r"(0u), "r"(acc)
        : "memory");
}

__device__ __forceinline__ void mbar_wait(uint32_t mbar, uint32_t parity) {
    asm volatile(
        "{\n\t.reg .pred P;\n"
        "W_%=:\n\tmbarrier.try_wait.parity.acquire.cta.shared::cta.b64 P, [%0], %1, 0x989680;\n"
        "\t@P bra.uni D_%=;\n\tbra.uni W_%=;\n"
        "D_%=:\n\t}\n"
        :: "r"(mbar), "r"(parity) : "memory");
}

#define LDTM_X32(r, addr) \
    asm volatile( \
        "tcgen05.ld.sync.aligned.32x32b.x32.b32 " \
        "{%0, %1, %2, %3, %4, %5, %6, %7, " \
        " %8, %9, %10, %11, %12, %13, %14, %15, " \
        " %16, %17, %18, %19, %20, %21, %22, %23, " \
        " %24, %25, %26, %27, %28, %29, %30, %31}, [%32];" \
        : "=r"((r)[0]),  "=r"((r)[1]),  "=r"((r)[2]),  "=r"((r)[3]), \
          "=r"((r)[4]),  "=r"((r)[5]),  "=r"((r)[6]),  "=r"((r)[7]), \
          "=r"((r)[8]),  "=r"((r)[9]),  "=r"((r)[10]), "=r"((r)[11]), \
          "=r"((r)[12]), "=r"((r)[13]), "=r"((r)[14]), "=r"((r)[15]), \
          "=r"((r)[16]), "=r"((r)[17]), "=r"((r)[18]), "=r"((r)[19]), \
          "=r"((r)[20]), "=r"((r)[21]), "=r"((r)[22]), "=r"((r)[23]), \
          "=r"((r)[24]), "=r"((r)[25]), "=r"((r)[26]), "=r"((r)[27]), \
          "=r"((r)[28]), "=r"((r)[29]), "=r"((r)[30]), "=r"((r)[31]) \
        : "r"(addr))

// Issue one K=64 chunk: 4 k-steps x 3 split-products (hi*hi + hi*lo + lo*hi).
// aBuf: [Ah | Al] at +0/+16384.  bBuf: [Bh | Bl] at +0/+16384.
__device__ __forceinline__ void issue_chunk2(uint32_t d, uint32_t aBuf, uint32_t bBuf,
                                             int accum0, uint32_t mbar) {
    uint64_t ah = mk_desc(aBuf), al = mk_desc(aBuf + 16384);
    uint64_t bh = mk_desc(bBuf), bl = mk_desc(bBuf + 16384);
#pragma unroll
    for (int ks = 0; ks < 4; ks++) {
        mma_f16_ss(d, ah + ks * 2, bh + ks * 2, (ks == 0) ? (uint32_t)accum0 : 1u);
        mma_f16_ss(d, ah + ks * 2, bl + ks * 2, 1u);
        mma_f16_ss(d, al + ks * 2, bh + ks * 2, 1u);
    }
    asm volatile(
        "tcgen05.commit.cta_group::1.mbarrier::arrive::one.shared::cluster.b64 [%0];"
        :: "r"(mbar) : "memory");
}

// async-copy one 128x128B tile row (thread tid owns row tid) with SW128 swizzle
__device__ __forceinline__ void load_tile_async(uint32_t sdst, int tid,
                                                const __nv_bfloat16* src) {
#pragma unroll
    for (int i = 0; i < 8; i++) {
        uint32_t bo = (uint32_t)tid * 128 + i * 16;
        uint32_t sw = bo ^ ((bo >> 3) & 0x70);
        asm volatile("cp.async.cg.shared.global [%0], [%1], 16;"
                     :: "r"(sdst + sw), "l"((const char*)src + i * 16) : "memory");
    }
}

// hi tile to base, lo tile to base+16384
__device__ __forceinline__ void load_pair_async(uint32_t sdst, int tid,
                                                const __nv_bfloat16* hi,
                                                const __nv_bfloat16* lo) {
    load_tile_async(sdst,         tid, hi);
    load_tile_async(sdst + 16384, tid, lo);
}

// Double-buffered pipelined GEMM mainloop (lstm): 8 chunks of K=64.
__device__ __forceinline__ void run_pipeline8(uint32_t smem_base, uint32_t tmem,
                                              uint32_t mbar, int tid, int wid,
                                              const __nv_bfloat16* Ah,
                                              const __nv_bfloat16* Al,
                                              const __nv_bfloat16* Bh,
                                              const __nv_bfloat16* Bl) {
    {
        uint32_t s0 = smem_base + SM_BUF(0);
        load_pair_async(s0,         tid, Ah, Al);
        load_pair_async(s0 + 32768, tid, Bh, Bl);
        asm volatile("cp.async.commit_group;" ::: "memory");
    }
#pragma unroll
    for (int ch = 0; ch < 8; ch++) {
        uint32_t sbuf = smem_base + SM_BUF(ch & 1);
        if (ch + 1 < 8) {
            if (ch >= 1) mbar_wait(mbar, (uint32_t)((ch - 1) & 1));
            uint32_t sn = smem_base + SM_BUF((ch + 1) & 1);
            int kk = (ch + 1) * 64;
            load_pair_async(sn,         tid, Ah + kk, Al + kk);
            load_pair_async(sn + 32768, tid, Bh + kk, Bl + kk);
            asm volatile("cp.async.commit_group;" ::: "memory");
            asm volatile("cp.async.wait_group 1;" ::: "memory");
        } else {
            asm volatile("cp.async.wait_group 0;" ::: "memory");
        }
        asm volatile("fence.proxy.async.shared::cta;" ::: "memory");
        __syncthreads();
        if (wid == 0 && elect_one())
            issue_chunk2(tmem, sbuf, sbuf + 32768, ch != 0, mbar);
    }
    mbar_wait(mbar, 0u);
    mbar_wait(mbar, 1u);
    asm volatile("tcgen05.fence::after_thread_sync;" ::: "memory");
}
#endif  // HAS_TC

// ---------------------------------------------------------------------------
// init + split kernels
// ---------------------------------------------------------------------------
__global__ void init_state_kernel() {
    int idx = blockIdx.x * blockDim.x + threadIdx.x;
    if (idx < R_ * H_) {
        g_Hhi[0][idx] = __float2bfloat16(0.f);
        g_Hlo[0][idx] = __float2bfloat16(0.f);
    }
    if (idx < NCTA) g_flags[idx] = 0;
}

__global__ void split_emb_kernel(const float* __restrict__ emb) {
    size_t idx = (size_t)blockIdx.x * blockDim.x + threadIdx.x;
    if (idx >= (size_t)V_ * EP_) return;
    int k = (int)(idx % EP_);
    size_t v = idx / EP_;
    float x = (k < E_) ? emb[v * E_ + k] : 0.f;
    __nv_bfloat16 hi = __float2bfloat16(x);
    g_Ehi[idx] = hi;
    g_Elo[idx] = __float2bfloat16(x - __bfloat162float(hi));
}

// Wx transposed + gate-permuted: out[n_perm][k], n_perm = hcol*4+g, src col = g*512+hcol
__global__ void split_wx_kernel(const float* __restrict__ kern) {
    int idx = blockIdx.x * blockDim.x + threadIdx.x;
    if (idx >= N4H * EP_) return;
    int n = idx / EP_, k = idx % EP_;
    int nsrc = (n & 3) * H_ + (n >> 2);
    float x = (k < E_) ? kern[(size_t)k * N4H + nsrc] : 0.f;
    __nv_bfloat16 hi = __float2bfloat16(x);
    g_WxThi[idx] = hi;
    g_WxTlo[idx] = __float2bfloat16(x - __bfloat162float(hi));
}

__global__ void split_wh_kernel(const float* __restrict__ kern) {
    int idx = blockIdx.x * blockDim.x + threadIdx.x;
    if (idx >= N4H * KH_) return;
    int n = idx / KH_, k = idx % KH_;
    int nsrc = (n & 3) * H_ + (n >> 2);
    float x = kern[(size_t)(E_ + k) * N4H + nsrc];
    __nv_bfloat16 hi = __float2bfloat16(x);
    g_WhThi[idx] = hi;
    g_WhTlo[idx] = __float2bfloat16(x - __bfloat162float(hi));
}

// ---------------------------------------------------------------------------
// x-projection: XZ[t][r][n_perm] = emb[token] @ Wx + bias
//   grid: (4 N-groups, 480 M-tiles), 128 threads.
//   Each CTA: 1 M-tile x 4 N-tiles; D = 4x128 TMEM cols; A loaded once per
//   chunk and reused for all 4 N-tiles.
// ---------------------------------------------------------------------------
__global__ __launch_bounds__(128)
void xproj_kernel(const int* __restrict__ in1, const int* __restrict__ in2,
                  const float* __restrict__ bias)
{
    const int tid = threadIdx.x;
    const int bx = blockIdx.x;             // N-group (4 tiles of 128)
    const int m0 = blockIdx.y * 128;
    const int t  = m0 >> 10;

    const int rr = (m0 & 1023) + tid;
    const int bb = rr & 511;
    const int token = (rr < 512) ? in1[bb * T_ + t] : in2[bb * T_ + t];

#if HAS_TC
    extern __shared__ char smem[];
    const int wid = tid >> 5;
    const int lane = tid & 31;
    uint32_t smem_base = smem_u32(smem);
    uint32_t mbar = smem_base + 8;

    if (wid == 0) {
        asm volatile("tcgen05.alloc.cta_group::1.sync.aligned.shared::cta.b32 [%0], %1;"
                     :: "r"(smem_base), "r"(512u) : "memory");
        asm volatile("tcgen05.relinquish_alloc_permit.cta_group::1.sync.aligned;");
    }
    if (tid == 0)
        asm volatile("mbarrier.init.shared.b64 [%0], 1;" :: "r"(mbar) : "memory");
    __syncthreads();
    uint32_t tmem;
    asm volatile("ld.shared.b32 %0, [%1];" : "=r"(tmem) : "r"(smem_base));

    const __nv_bfloat16* Ah = g_Ehi + (size_t)token * EP_;
    const __nv_bfloat16* Al = g_Elo + (size_t)token * EP_;
    const __nv_bfloat16* BhBase[4];
    const __nv_bfloat16* BlBase[4];
#pragma unroll
    for (int nt = 0; nt < 4; nt++) {
        int n = (bx * 4 + nt) * 128 + tid;
        BhBase[nt] = g_WxThi + (size_t)n * EP_;
        BlBase[nt] = g_WxTlo + (size_t)n * EP_;
    }

    // prologue: A chunk0 + B(nt=0, ch=0)
    load_pair_async(smem_base + XA_BUF(0), tid, Ah, Al);
    load_pair_async(smem_base + XB_BUF(0), tid, BhBase[0], BlBase[0]);
    asm volatile("cp.async.commit_group;" ::: "memory");

#pragma unroll
    for (int i = 0; i < 20; i++) {
        const int ch = i >> 2, nt = i & 3;
        if (i + 1 < 20) {
            if (i >= 1) mbar_wait(mbar, (uint32_t)((i - 1) & 1));
            const int ni = i + 1, nch = ni >> 2, nnt = ni & 3;
            if (nnt == 0)
                load_pair_async(smem_base + XA_BUF(nch & 1), tid,
                                Ah + nch * 64, Al + nch * 64);
            load_pair_async(smem_base + XB_BUF(ni & 1), tid,
                            BhBase[nnt] + nch * 64, BlBase[nnt] + nch * 64);
            asm volatile("cp.async.commit_group;" ::: "memory");
            asm volatile("cp.async.wait_group 1;" ::: "memory");
        } else {
            asm volatile("cp.async.wait_group 0;" ::: "memory");
        }
        asm volatile("fence.proxy.async.shared::cta;" ::: "memory");
        __syncthreads();
        if (wid == 0 && elect_one())
            issue_chunk2(tmem + nt * 128,
                         smem_base + XA_BUF(ch & 1),
                         smem_base + XB_BUF(i & 1), ch != 0, mbar);
    }
    mbar_wait(mbar, 0u);
    mbar_wait(mbar, 1u);
    asm volatile("tcgen05.fence::after_thread_sync;" ::: "memory");

    // epilogue: D[nt] + bias -> XZ (permuted layout)
    const int m = m0 + wid * 32 + lane;
#pragma unroll
    for (int nt = 0; nt < 4; nt++) {
        const int n0nt = (bx * 4 + nt) * 128;
        const int hc0 = (bx * 4 + nt) * 32;
        float* dst = g_XZ + (size_t)m * N4H + n0nt;
#pragma unroll
        for (int cg = 0; cg < 4; cg++) {
            uint32_t d[32];
            LDTM_X32(d, tmem + nt * 128 + cg * 32);
            asm volatile("tcgen05.wait::ld.sync.aligned;" ::: "memory");
#pragma unroll
            for (int hh = 0; hh < 8; hh++) {
                int hcol = hc0 + cg * 8 + hh;
                float4 v;
                v.x = __uint_as_float(d[hh * 4 + 0]) + bias[0 * H_ + hcol];
                v.y = __uint_as_float(d[hh * 4 + 1]) + bias[1 * H_ + hcol];
                v.z = __uint_as_float(d[hh * 4 + 2]) + bias[2 * H_ + hcol];
                v.w = __uint_as_float(d[hh * 4 + 3]) + bias[3 * H_ + hcol];
                *(float4*)(dst + cg * 32 + hh * 4) = v;
            }
        }
    }
    __syncthreads();
    if (tid == 0)
        asm volatile("mbarrier.inval.shared.b64 [%0];" :: "r"(mbar) : "memory");
    if (wid == 0)
        asm volatile("tcgen05.dealloc.cta_group::1.sync.aligned.b32 %0, %1;"
                     :: "r"(tmem), "r"(512u));
#else
    // FFMA fallback (non-'a' gencode pass; never runs on GB300)
    const __nv_bfloat16* Ah = g_Ehi + (size_t)token * EP_;
    const __nv_bfloat16* Al = g_Elo + (size_t)token * EP_;
    float* dst = g_XZ + (size_t)(m0 + tid) * N4H;
    for (int n = bx * 512; n < bx * 512 + 512; n++) {
        float acc = 0.f;
        for (int k = 0; k < EP_; k++) {
            float a = __bfloat162float(Ah[k]) + __bfloat162float(Al[k]);
            size_t bi = (size_t)n * EP_ + k;
            float b = __bfloat162float(g_WxThi[bi]) + __bfloat162float(g_WxTlo[bi]);
            acc = fmaf(a, b, acc);
        }
        dst[n] = acc + bias[(n & 3) * H_ + (n >> 2)];
    }
#endif
}

// ---------------------------------------------------------------------------
// PERSISTENT fused LSTM: one launch, 60 steps, grid (16 N-tiles, 8 M-tiles),
// 128 threads. C/H state lives in registers; inter-step gmem flag barrier.
// ---------------------------------------------------------------------------
__global__ __launch_bounds__(128)
void lstm_persist_kernel(const int* __restrict__ sl1, const int* __restrict__ sl2)
{
    const int tid = threadIdx.x;
    const int n0 = blockIdx.x * 128;
    const int m0 = blockIdx.y * 128;
    const int cta = blockIdx.y * 16 + blockIdx.x;

#if HAS_TC
    extern __shared__ char smem[];
    const int wid = tid >> 5;
    const int lane = tid & 31;
    uint32_t smem_base = smem_u32(smem);
    uint32_t mbar = smem_base + 8;

    if (wid == 0) {
        asm volatile("tcgen05.alloc.cta_group::1.sync.aligned.shared::cta.b32 [%0], %1;"
                     :: "r"(smem_base), "r"(128u) : "memory");
        asm volatile("tcgen05.relinquish_alloc_permit.cta_group::1.sync.aligned;");
    }
    if (tid == 0)
        asm volatile("mbarrier.init.shared.b64 [%0], 1;" :: "r"(mbar) : "memory");
    __syncthreads();
    uint32_t tmem;
    asm volatile("ld.shared.b32 %0, [%1];" : "=r"(tmem) : "r"(smem_base));

    const int r = m0 + wid * 32 + lane;
    const int b = r & 511;
    const int sl = (r < 512) ? sl1[b] : sl2[b];
    const int hc0 = blockIdx.x * 32;
    const int idx0 = r * H_ + hc0;

    const __nv_bfloat16* AhB[2] = { g_Hhi[0] + (size_t)(m0 + tid) * KH_,
                                    g_Hhi[1] + (size_t)(m0 + tid) * KH_ };
    const __nv_bfloat16* AlB[2] = { g_Hlo[0] + (size_t)(m0 + tid) * KH_,
                                    g_Hlo[1] + (size_t)(m0 + tid) * KH_ };
    const __nv_bfloat16* Bh = g_WhThi + (size_t)(n0 + tid) * KH_;
    const __nv_bfloat16* Bl = g_WhTlo + (size_t)(n0 + tid) * KH_;

    float c[32], h[32];
#pragma unroll
    for (int j = 0; j < 32; j++) { c[j] = 0.f; h[j] = 0.f; }

    for (int t = 0; t < T_; t++) {
        const int rb = t & 1, wb = (t + 1) & 1;

        run_pipeline8(smem_base, tmem, mbar, tid, wid, AhB[rb], AlB[rb], Bh, Bl);

        // fused gates epilogue, state in registers
        const bool valid = (t < sl);
        const float* xz = g_XZ + ((size_t)t * R_ + r) * N4H + n0;

#pragma unroll
        for (int cg = 0; cg < 4; cg++) {
            float4 xv[8];
#pragma unroll
            for (int hh = 0; hh < 8; hh++)
                xv[hh] = *(const float4*)(xz + cg * 32 + hh * 4);
            uint32_t d[32];
            LDTM_X32(d, tmem + cg * 32);
            asm volatile("tcgen05.wait::ld.sync.aligned;" ::: "memory");
#pragma unroll
            for (int hh = 0; hh < 8; hh++) {
                int j = cg * 8 + hh;
                float zi = __uint_as_float(d[hh * 4 + 0]) + xv[hh].x;
                float zj = __uint_as_float(d[hh * 4 + 1]) + xv[hh].y;
                float zf = __uint_as_float(d[hh * 4 + 2]) + xv[hh].z;
                float zo = __uint_as_float(d[hh * 4 + 3]) + xv[hh].w;
                float nc = c[j] * sigmoidf_(zf + 1.f) + sigmoidf_(zi) * tanhf(zj);
                float nh = tanhf(nc) * sigmoidf_(zo);
                if (valid) { c[j] = nc; h[j] = nh; }
            }
        }
        asm volatile("tcgen05.fence::before_thread_sync;" ::: "memory");

        if (t < T_ - 1) {
            // write H splits for next step's A tiles (buffer wb)
            uint32_t hi2[16], lo2[16];
#pragma unroll
            for (int j = 0; j < 16; j++) {
                float h0 = h[j * 2], h1 = h[j * 2 + 1];
                __nv_bfloat16 b0 = __float2bfloat16(h0);
                __nv_bfloat16 b1 = __float2bfloat16(h1);
                __nv_bfloat16 l0 = __float2bfloat16(h0 - __bfloat162float(b0));
                __nv_bfloat16 l1 = __float2bfloat16(h1 - __bfloat162float(b1));
                hi2[j] = (uint32_t)__bfloat16_as_ushort(b0) |
                         ((uint32_t)__bfloat16_as_ushort(b1) << 16);
                lo2[j] = (uint32_t)__bfloat16_as_ushort(l0) |
                         ((uint32_t)__bfloat16_as_ushort(l1) << 16);
            }
#pragma unroll
            for (int i = 0; i < 4; i++) {
                *(uint4*)(g_Hhi[wb] + idx0 + i * 8) = *(const uint4*)&hi2[i * 4];
                *(uint4*)(g_Hlo[wb] + idx0 + i * 8) = *(const uint4*)&lo2[i * 4];
            }

            // grid barrier: release flag, acquire-poll all flags
            __syncthreads();
            __threadfence();
            if (tid == 0) {
                asm volatile("st.release.gpu.global.s32 [%0], %1;"
                             :: "l"(&g_flags[cta]), "r"(t + 1) : "memory");
            }
            {
                int v;
                const int* fp = &g_flags[tid];   // blockDim == NCTA == 128
                do {
                    asm volatile("ld.acquire.gpu.global.s32 %0, [%1];"
                                 : "=r"(v) : "l"(fp) : "memory");
                    if (v > t) break;
                    __nanosleep(64);
                } while (true);
            }
            __syncthreads();
        } else {
            // final step: publish h for the head kernel
#pragma unroll
            for (int i = 0; i < 8; i++)
                *(float4*)(g_H + idx0 + i * 4) = *(const float4*)&h[i * 4];
        }
    }

    __syncthreads();
    if (tid == 0)
        asm volatile("mbarrier.inval.shared.b64 [%0];" :: "r"(mbar) : "memory");
    if (wid == 0)
        asm volatile("tcgen05.dealloc.cta_group::1.sync.aligned.b32 %0, %1;"
                     :: "r"(tmem), "r"(128u));
#else
    // FFMA fallback (non-'a' gencode pass; never runs on GB300).
    const int r = m0 + tid;
    const int b = r & 511;
    const int sl = (r < 512) ? sl1[b] : sl2[b];
    const int hc0 = blockIdx.x * 32;
    float c[32], h[32];
    for (int j = 0; j < 32; j++) { c[j] = 0.f; h[j] = 0.f; }

    for (int t = 0; t < T_; t++) {
        const int rb = t & 1, wb = (t + 1) & 1;
        const bool valid = (t < sl);
        const float* xz = g_XZ + ((size_t)t * R_ + r) * N4H;
        const __nv_bfloat16* Ah = g_Hhi[rb] + (size_t)r * KH_;
        const __nv_bfloat16* Al = g_Hlo[rb] + (size_t)r * KH_;

        for (int j = 0; j < 32; j++) {
            int n = (hc0 + j) * 4;
            float acc[4] = {0, 0, 0, 0};
            for (int k = 0; k < KH_; k++) {
                float a = __bfloat162float(Ah[k]) + __bfloat162float(Al[k]);
                for (int g = 0; g < 4; g++) {
                    size_t bi = (size_t)(n + g) * KH_ + k;
                    float bw = __bfloat162float(g_WhThi[bi]) + __bfloat162float(g_WhTlo[bi]);
                    acc[g] = fmaf(a, bw, acc[g]);
                }
            }
            float zi = acc[0] + xz[n + 0];
            float zj = acc[1] + xz[n + 1];
            float zf = acc[2] + xz[n + 2];
            float zo = acc[3] + xz[n + 3];
            float nc = c[j] * sigmoidf_(zf + 1.f) + sigmoidf_(zi) * tanhf(zj);
            float nh = tanhf(nc) * sigmoidf_(zo);
            if (valid) { c[j] = nc; h[j] = nh; }
        }
        if (t < T_ - 1) {
            for (int j = 0; j < 32; j++) {
                int idx = r * H_ + hc0 + j;
                __nv_bfloat16 hb = __float2bfloat16(h[j]);
                g_Hhi[wb][idx] = hb;
                g_Hlo[wb][idx] = __float2bfloat16(h[j] - __bfloat162float(hb));
            }
            __syncthreads();
            __threadfence();
            if (tid == 0) atomicExch(&g_flags[cta], t + 1);
            volatile int* fp = (volatile int*)&g_flags[tid];
            while (*fp <= t) { __nanosleep(64); }
            __threadfence();
            __syncthreads();
        } else {
            for (int j = 0; j < 32; j++) g_H[r * H_ + hc0 + j] = h[j];
        }
    }
#endif
}

// ---------------------------------------------------------------------------
// head (not a bottleneck)
// ---------------------------------------------------------------------------
__global__ __launch_bounds__(256)
void head_kernel(const int* __restrict__ sl1, const int* __restrict__ sl2,
                 const float* __restrict__ W1, const float* __restrict__ b1,
                 const float* __restrict__ W2, const float* __restrict__ b2,
                 float* __restrict__ out)
{
    __shared__ float hcs[4][2053];
    __shared__ float e1s[4][256];
    __shared__ float red[256];

    const int tid = threadIdx.x;
    const int b0  = blockIdx.x * 4;

    for (int rr = 0; rr < 4; rr++) {
        int bb = b0 + rr;
        const float* h1 = g_H + (size_t)bb * H_;
        const float* h2 = g_H + (size_t)(512 + bb) * H_;
        for (int k = tid; k < H_; k += 256) {
            float a = h1[k], c = h2[k];
            hcs[rr][k]        = a;
            hcs[rr][513 + k]  = c;
            hcs[rr][1026 + k] = a - c;
            hcs[rr][1540 + k] = a * c;
        }
        if (tid == 0) {
            float l1 = (float)sl1[bb] / (float)T_;
            float l2 = (float)sl2[bb] / (float)T_;
            hcs[rr][512]  = l1;
            hcs[rr][1025] = l2;
            hcs[rr][1538] = l1 - l2;
            hcs[rr][2052] = l1 * l2;
        }
    }
    __syncthreads();

    for (int rr = 0; rr < 4; rr++) {
        float v = 0.f;
        for (int k = tid; k < 513; k += 256) {
            float s = hcs[rr][1026 + k];
            v += s * s;
        }
        red[tid] = v;
        __syncthreads();
        for (int s = 128; s > 0; s >>= 1) {
            if (tid < s) red[tid] += red[tid + s];
            __syncthreads();
        }
        if (tid == 0) hcs[rr][1539] = red[0];
        __syncthreads();
    }

    float a0 = b1[tid], a1 = b1[tid], a2 = b1[tid], a3 = b1[tid];
    for (int k = 0; k < 2053; k++) {
        float w = W1[(size_t)k * M_ + tid];
        a0 = fmaf(hcs[0][k], w, a0);
        a1 = fmaf(hcs[1][k], w, a1);
        a2 = fmaf(hcs[2][k], w, a2);
        a3 = fmaf(hcs[3][k], w, a3);
    }
    e1s[0][tid] = fmaxf(a0, 0.f);
    e1s[1][tid] = fmaxf(a1, 0.f);
    e1s[2][tid] = fmaxf(a2, 0.f);
    e1s[3][tid] = fmaxf(a3, 0.f);
    __syncthreads();

    int wid  = tid >> 5;
    int lane = tid & 31;
    int rr   = wid >> 1;
    int j    = wid & 1;
    float s = 0.f;
    for (int k = lane; k < M_; k += 32)
        s = fmaf(e1s[rr][k], W2[k * 2 + j], s);
#pragma unroll
    for (int off = 16; off > 0; off >>= 1)
        s += __shfl_down_sync(0xffffffffu, s, off);
    if (lane == 0)
        out[(size_t)(b0 + rr) * 2 + j] = s + b2[j];
}

// ---------------------------------------------------------------------------
// launch
// ---------------------------------------------------------------------------
extern "C" void kernel_launch(void* const* d_in, const int* in_sizes, int n_in,
                              void* d_out, int out_size)
{
    const int*   input1  = (const int*)  d_in[0];
    const int*   input2  = (const int*)  d_in[1];
    const int*   seqlen1 = (const int*)  d_in[2];
    const int*   seqlen2 = (const int*)  d_in[3];
    const float* emb     = (const float*)d_in[4];
    const float* kern    = (const float*)d_in[5];
    const float* bias    = (const float*)d_in[6];
    const float* W1      = (const float*)d_in[7];
    const float* b1      = (const float*)d_in[8];
    const float* W2      = (const float*)d_in[9];
    const float* b2      = (const float*)d_in[10];
    float*       out     = (float*)d_out;

    cudaFuncSetAttribute(xproj_kernel, cudaFuncAttributeMaxDynamicSharedMemorySize, SMEM_BYTES);
    cudaFuncSetAttribute(lstm_persist_kernel, cudaFuncAttributeMaxDynamicSharedMemorySize, SMEM_BYTES);

    init_state_kernel<<<(R_ * H_ + 255) / 256, 256>>>();
    split_emb_kernel<<<(int)(((size_t)V_ * EP_ + 255) / 256), 256>>>(emb);
    split_wx_kernel<<<(N4H * EP_ + 255) / 256, 256>>>(kern);
    split_wh_kernel<<<(N4H * KH_ + 255) / 256, 256>>>(kern);

    // x-projection for all timesteps, both sequences
    xproj_kernel<<<dim3(4, (T_ * R_) / 128), 128, SMEM_BYTES>>>(input1, input2, bias);

    // persistent recurrence: one launch, 60 steps, register-resident state
    lstm_persist_kernel<<<dim3(16, 8), 128, SMEM_BYTES>>>(seqlen1, seqlen2);

    head_kernel<<<B_ / 4, 256>>>(seqlen1, seqlen2, W1, b1, W2, b2, out);
}

// round 8
// speedup vs baseline: 1.1642x; 1.1642x over previous
#include <cuda_runtime.h>
#include <cuda_bf16.h>
#include <math.h>
#include <stdint.h>

#define B_   512
#define T_   60
#define V_   50000
#define E_   300
#define EP_  320          // E padded to multiple of 64
#define H_   512
#define M_   256
#define R_   1024         // 2*B rows (both sequences batched)
#define N4H  2048         // 4*H (gate-interleaved permuted layout)
#define KH_  512
#define NCTA 128
#define GRP_ 16           // CTAs per M-tile row group

// Feature gate: tcgen05 only exists in the arch-specific (sm_103a/sm_100a)
// compilation passes. The plain compute_103/sm_103 pass gets an FFMA fallback.
#if defined(__CUDA_ARCH__) && (defined(__CUDA_ARCH_FEAT_SM103_ALL) || \
                               defined(__CUDA_ARCH_FEAT_SM100_ALL) || \
                               (defined(__CUDA_ARCH_SPECIFIC__) && (__CUDA_ARCH_SPECIFIC__ >= 1000)))
#define HAS_TC 1
#else
#define HAS_TC 0
#endif

// ---------------------------------------------------------------------------
// Device scratch (static allocations — allowed)
// ---------------------------------------------------------------------------
__device__ __align__(16) float g_XZ[(size_t)T_ * R_ * N4H];   // x-proj + bias, SORTED rows
__device__ __align__(16) float g_H[R_ * H_];                  // final h, ORIGINAL rows
__device__ __align__(16) __nv_bfloat16 g_Hhi[2][R_ * H_];     // ping-pong H splits (sorted rows)
__device__ __align__(16) __nv_bfloat16 g_Hlo[2][R_ * H_];
__device__ __align__(16) __nv_bfloat16 g_Ehi[(size_t)V_ * EP_];
__device__ __align__(16) __nv_bfloat16 g_Elo[(size_t)V_ * EP_];
__device__ __align__(16) __nv_bfloat16 g_WxThi[N4H * EP_];    // [n_perm][k], K-major
__device__ __align__(16) __nv_bfloat16 g_WxTlo[N4H * EP_];
__device__ __align__(16) __nv_bfloat16 g_WhThi[N4H * KH_];
__device__ __align__(16) __nv_bfloat16 g_WhTlo[N4H * KH_];
__device__ int g_perm[R_];        // sorted pos -> original row
__device__ int g_slsort[R_];      // seqlen at sorted pos (ascending per half)
__device__ int g_tilemax[8];      // max seqlen per 128-row tile
__device__ int g_flags[NCTA];     // per-CTA barrier flags (grouped 16 per row tile)

__device__ __forceinline__ float sigmoidf_(float x) { return 1.f / (1.f + expf(-x)); }

// SMEM layouts (both GEMM kernels: 132096 B)
#define XA_BUF(b)    (1024 + (b) * 32768)
#define XB_BUF(b)    (1024 + 65536 + (b) * 32768)
#define LS_BUF(b)    (1024 + (b) * 65536)
#define SMEM_BYTES   (1024 + 2 * 65536)

#if HAS_TC
// ---------------------------------------------------------------------------
// PTX helpers (sm_103a only)
// ---------------------------------------------------------------------------
__device__ __forceinline__ uint32_t smem_u32(const void* p) {
    uint32_t a;
    asm("{ .reg .u64 t; cvta.to.shared.u64 t, %1; cvt.u32.u64 %0, t; }" : "=r"(a) : "l"(p));
    return a;
}
__device__ __forceinline__ uint32_t elect_one() {
    uint32_t p;
    asm volatile("{ .reg .pred p; elect.sync _|p, 0xFFFFFFFF; selp.b32 %0, 1, 0, p; }" : "=r"(p));
    return p;
}

// idesc: c=F32, a=BF16 K-major, b=BF16 K-major, M=128, N=128
#define IDESC_128x128 0x8200490u
// SW128 desc base: layout=2, version=1, SBO=64, LBO=1
#define DESC_BASE ((2ull << 61) | (1ull << 46) | (64ull << 32) | (1ull << 16))

__device__ __forceinline__ uint64_t mk_desc(uint32_t smem_addr) {
    return DESC_BASE | ((uint64_t)(smem_addr >> 4) & 0x3FFF);
}

__device__ __forceinline__ void mma_f16_ss(uint32_t d, uint64_t ad, uint64_t bd, uint32_t acc) {
    asm volatile(
        "{\n\t.reg .pred p;\n\tsetp.ne.u32 p, %5, 0;\n\t"
        "tcgen05.mma.cta_group::1.kind::f16 [%0], %1, %2, %3, {%4, %4, %4, %4}, p;\n\t}\n"
        :: "r"(d), "l"(ad), "l"(bd), "r"(IDESC_128x128), "r"(0u), "r"(acc)
        : "memory");
}

__device__ __forceinline__ void mbar_wait(uint32_t mbar, uint32_t parity) {
    asm volatile(
        "{\n\t.reg .pred P;\n"
        "W_%=:\n\tmbarrier.try_wait.parity.acquire.cta.shared::cta.b64 P, [%0], %1, 0x989680;\n"
        "\t@P bra.uni D_%=;\n\tbra.uni W_%=;\n"
        "D_%=:\n\t}\n"
        :: "r"(mbar), "r"(parity) : "memory");
}

#define LDTM_X32(r, addr) \
    asm volatile( \
        "tcgen05.ld.sync.aligned.32x32b.x32.b32 " \
        "{%0, %1, %2, %3, %4, %5, %6, %7, " \
        " %8, %9, %10, %11, %12, %13, %14, %15, " \
        " %16, %17, %18, %19, %20, %21, %22, %23, " \
        " %24, %25, %26, %27, %28, %29, %30, %31}, [%32];" \
        : "=r"((r)[0]),  "=r"((r)[1]),  "=r"((r)[2]),  "=r"((r)[3]), \
          "=r"((r)[4]),  "=r"((r)[5]),  "=r"((r)[6]),  "=r"((r)[7]), \
          "=r"((r)[8]),  "=r"((r)[9]),  "=r"((r)[10]), "=r"((r)[11]), \
          "=r"((r)[12]), "=r"((r)[13]), "=r"((r)[14]), "=r"((r)[15]), \
          "=r"((r)[16]), "=r"((r)[17]), "=r"((r)[18]), "=r"((r)[19]), \
          "=r"((r)[20]), "=r"((r)[21]), "=r"((r)[22]), "=r"((r)[23]), \
          "=r"((r)[24]), "=r"((r)[25]), "=r"((r)[26]), "=r"((r)[27]), \
          "=r"((r)[28]), "=r"((r)[29]), "=r"((r)[30]), "=r"((r)[31]) \
        : "r"(addr))

// Issue one K=64 chunk: 4 k-steps x 3 split-products (hi*hi + hi*lo + lo*hi).
__device__ __forceinline__ void issue_chunk2(uint32_t d, uint32_t aBuf, uint32_t bBuf,
                                             int accum0, uint32_t mbar) {
    uint64_t ah = mk_desc(aBuf), al = mk_desc(aBuf + 16384);
    uint64_t bh = mk_desc(bBuf), bl = mk_desc(bBuf + 16384);
#pragma unroll
    for (int ks = 0; ks < 4; ks++) {
        mma_f16_ss(d, ah + ks * 2, bh + ks * 2, (ks == 0) ? (uint32_t)accum0 : 1u);
        mma_f16_ss(d, ah + ks * 2, bl + ks * 2, 1u);
        mma_f16_ss(d, al + ks * 2, bh + ks * 2, 1u);
    }
    asm volatile(
        "tcgen05.commit.cta_group::1.mbarrier::arrive::one.shared::cluster.b64 [%0];"
        :: "r"(mbar) : "memory");
}

// async-copy one 128x128B tile row (thread tid owns row tid) with SW128 swizzle
__device__ __forceinline__ void load_tile_async(uint32_t sdst, int tid,
                                                const __nv_bfloat16* src) {
#pragma unroll
    for (int i = 0; i < 8; i++) {
        uint32_t bo = (uint32_t)tid * 128 + i * 16;
        uint32_t sw = bo ^ ((bo >> 3) & 0x70);
        asm volatile("cp.async.cg.shared.global [%0], [%1], 16;"
                     :: "r"(sdst + sw), "l"((const char*)src + i * 16) : "memory");
    }
}
__device__ __forceinline__ void load_pair_async(uint32_t sdst, int tid,
                                                const __nv_bfloat16* hi,
                                                const __nv_bfloat16* lo) {
    load_tile_async(sdst,         tid, hi);
    load_tile_async(sdst + 16384, tid, lo);
}

// Double-buffered pipelined GEMM mainloop (lstm): 8 chunks of K=64.
__device__ __forceinline__ void run_pipeline8(uint32_t smem_base, uint32_t tmem,
                                              uint32_t mbar, int tid, int wid,
                                              const __nv_bfloat16* Ah,
                                              const __nv_bfloat16* Al,
                                              const __nv_bfloat16* Bh,
                                              const __nv_bfloat16* Bl) {
    {
        uint32_t s0 = smem_base + LS_BUF(0);
        load_pair_async(s0,         tid, Ah, Al);
        load_pair_async(s0 + 32768, tid, Bh, Bl);
        asm volatile("cp.async.commit_group;" ::: "memory");
    }
#pragma unroll
    for (int ch = 0; ch < 8; ch++) {
        uint32_t sbuf = smem_base + LS_BUF(ch & 1);
        if (ch + 1 < 8) {
            if (ch >= 1) mbar_wait(mbar, (uint32_t)((ch - 1) & 1));
            uint32_t sn = smem_base + LS_BUF((ch + 1) & 1);
            int kk = (ch + 1) * 64;
            load_pair_async(sn,         tid, Ah + kk, Al + kk);
            load_pair_async(sn + 32768, tid, Bh + kk, Bl + kk);
            asm volatile("cp.async.commit_group;" ::: "memory");
            asm volatile("cp.async.wait_group 1;" ::: "memory");
        } else {
            asm volatile("cp.async.wait_group 0;" ::: "memory");
        }
        asm volatile("fence.proxy.async.shared::cta;" ::: "memory");
        __syncthreads();
        if (wid == 0 && elect_one())
            issue_chunk2(tmem, sbuf, sbuf + 32768, ch != 0, mbar);
    }
    mbar_wait(mbar, 0u);
    mbar_wait(mbar, 1u);
    asm volatile("tcgen05.fence::after_thread_sync;" ::: "memory");
}
#endif  // HAS_TC

// ---------------------------------------------------------------------------
// sort: counting sort of each 512-row half by seqlen (ascending), build perm,
// sorted seqlens, per-tile maxima, reset barrier flags. ONE block, 512 thr.
// ---------------------------------------------------------------------------
__global__ void sort_kernel(const int* __restrict__ sl1, const int* __restrict__ sl2) {
    __shared__ int cnt0[61], cnt1[61];
    __shared__ int base0[61], base1[61];
    const int tid = threadIdx.x;
    if (tid < 61) { cnt0[tid] = 0; cnt1[tid] = 0; }
    if (tid < NCTA) g_flags[tid] = 0;
    __syncthreads();
    const int s1 = sl1[tid], s2 = sl2[tid];
    atomicAdd(&cnt0[s1], 1);
    atomicAdd(&cnt1[s2], 1);
    __syncthreads();
    if (tid == 0) {
        int a = 0, b = 0;
        for (int k = 0; k < 61; k++) {
            base0[k] = a; a += cnt0[k];
            base1[k] = b; b += cnt1[k];
        }
    }
    __syncthreads();
    int p1 = atomicAdd(&base0[s1], 1);
    g_perm[p1] = tid;              g_slsort[p1] = s1;
    int p2 = atomicAdd(&base1[s2], 1);
    g_perm[512 + p2] = 512 + tid;  g_slsort[512 + p2] = s2;
    __syncthreads();
    if (tid < 8) g_tilemax[tid] = g_slsort[tid * 128 + 127];
}

// ---------------------------------------------------------------------------
// init + split kernels (identical to the R5 passing versions)
// ---------------------------------------------------------------------------
__global__ void init_state_kernel() {
    int idx = blockIdx.x * blockDim.x + threadIdx.x;
    if (idx < R_ * H_) {
        g_Hhi[0][idx] = __float2bfloat16(0.f);
        g_Hlo[0][idx] = __float2bfloat16(0.f);
    }
}

__global__ void split_emb_kernel(const float* __restrict__ emb) {
    size_t idx = (size_t)blockIdx.x * blockDim.x + threadIdx.x;
    if (idx >= (size_t)V_ * EP_) return;
    int k = (int)(idx % EP_);
    size_t v = idx / EP_;
    float x = (k < E_) ? emb[v * E_ + k] : 0.f;
    __nv_bfloat16 hi = __float2bfloat16(x);
    g_Ehi[idx] = hi;
    g_Elo[idx] = __float2bfloat16(x - __bfloat162float(hi));
}

__global__ void split_wx_kernel(const float* __restrict__ kern) {
    int idx = blockIdx.x * blockDim.x + threadIdx.x;
    if (idx >= N4H * EP_) return;
    int n = idx / EP_, k = idx % EP_;
    int nsrc = (n & 3) * H_ + (n >> 2);
    float x = (k < E_) ? kern[(size_t)k * N4H + nsrc] : 0.f;
    __nv_bfloat16 hi = __float2bfloat16(x);
    g_WxThi[idx] = hi;
    g_WxTlo[idx] = __float2bfloat16(x - __bfloat162float(hi));
}

__global__ void split_wh_kernel(const float* __restrict__ kern) {
    int idx = blockIdx.x * blockDim.x + threadIdx.x;
    if (idx >= N4H * KH_) return;
    int n = idx / KH_, k = idx % KH_;
    int nsrc = (n & 3) * H_ + (n >> 2);
    float x = kern[(size_t)(E_ + k) * N4H + nsrc];
    __nv_bfloat16 hi = __float2bfloat16(x);
    g_WhThi[idx] = hi;
    g_WhTlo[idx] = __float2bfloat16(x - __bfloat162float(hi));
}

// ---------------------------------------------------------------------------
// x-projection (sorted rows): XZ[t][r][n_perm] = emb[token(perm[r])]@Wx + bias
//   grid: (4 N-groups, 480 M-tiles), 128 threads; A reused across 4 N-tiles.
//   (t, tile) pairs with t >= tilemax(tile) exit immediately (XZ never read).
// ---------------------------------------------------------------------------
__global__ __launch_bounds__(128)
void xproj_kernel(const int* __restrict__ in1, const int* __restrict__ in2,
                  const float* __restrict__ bias)
{
    const int tid = threadIdx.x;
    const int bx = blockIdx.x;
    const int m0 = blockIdx.y * 128;
    const int t  = m0 >> 10;
    const int rb = m0 & 1023;

    if (t >= g_tilemax[rb >> 7]) return;

    const int rr = rb + tid;
    const int orig = g_perm[rr];
    const int bb = orig & 511;
    const int token = (orig < 512) ? in1[bb * T_ + t] : in2[bb * T_ + t];

#if HAS_TC
    extern __shared__ char smem[];
    const int wid = tid >> 5;
    const int lane = tid & 31;
    uint32_t smem_base = smem_u32(smem);
    uint32_t mbar = smem_base + 8;

    if (wid == 0) {
        asm volatile("tcgen05.alloc.cta_group::1.sync.aligned.shared::cta.b32 [%0], %1;"
                     :: "r"(smem_base), "r"(512u) : "memory");
        asm volatile("tcgen05.relinquish_alloc_permit.cta_group::1.sync.aligned;");
    }
    if (tid == 0)
        asm volatile("mbarrier.init.shared.b64 [%0], 1;" :: "r"(mbar) : "memory");
    __syncthreads();
    uint32_t tmem;
    asm volatile("ld.shared.b32 %0, [%1];" : "=r"(tmem) : "r"(smem_base));

    const __nv_bfloat16* Ah = g_Ehi + (size_t)token * EP_;
    const __nv_bfloat16* Al = g_Elo + (size_t)token * EP_;
    const __nv_bfloat16* BhBase[4];
    const __nv_bfloat16* BlBase[4];
#pragma unroll
    for (int nt = 0; nt < 4; nt++) {
        int n = (bx * 4 + nt) * 128 + tid;
        BhBase[nt] = g_WxThi + (size_t)n * EP_;
        BlBase[nt] = g_WxTlo + (size_t)n * EP_;
    }

    load_pair_async(smem_base + XA_BUF(0), tid, Ah, Al);
    load_pair_async(smem_base + XB_BUF(0), tid, BhBase[0], BlBase[0]);
    asm volatile("cp.async.commit_group;" ::: "memory");

#pragma unroll
    for (int i = 0; i < 20; i++) {
        const int ch = i >> 2, nt = i & 3;
        if (i + 1 < 20) {
            if (i >= 1) mbar_wait(mbar, (uint32_t)((i - 1) & 1));
            const int ni = i + 1, nch = ni >> 2, nnt = ni & 3;
            if (nnt == 0)
                load_pair_async(smem_base + XA_BUF(nch & 1), tid,
                                Ah + nch * 64, Al + nch * 64);
            load_pair_async(smem_base + XB_BUF(ni & 1), tid,
                            BhBase[nnt] + nch * 64, BlBase[nnt] + nch * 64);
            asm volatile("cp.async.commit_group;" ::: "memory");
            asm volatile("cp.async.wait_group 1;" ::: "memory");
        } else {
            asm volatile("cp.async.wait_group 0;" ::: "memory");
        }
        asm volatile("fence.proxy.async.shared::cta;" ::: "memory");
        __syncthreads();
        if (wid == 0 && elect_one())
            issue_chunk2(tmem + nt * 128,
                         smem_base + XA_BUF(ch & 1),
                         smem_base + XB_BUF(i & 1), ch != 0, mbar);
    }
    mbar_wait(mbar, 0u);
    mbar_wait(mbar, 1u);
    asm volatile("tcgen05.fence::after_thread_sync;" ::: "memory");

    const int m = m0 + wid * 32 + lane;
#pragma unroll
    for (int nt = 0; nt < 4; nt++) {
        const int n0nt = (bx * 4 + nt) * 128;
        const int hc0 = (bx * 4 + nt) * 32;
        float* dst = g_XZ + (size_t)m * N4H + n0nt;
#pragma unroll
        for (int cg = 0; cg < 4; cg++) {
            uint32_t d[32];
            LDTM_X32(d, tmem + nt * 128 + cg * 32);
            asm volatile("tcgen05.wait::ld.sync.aligned;" ::: "memory");
#pragma unroll
            for (int hh = 0; hh < 8; hh++) {
                int hcol = hc0 + cg * 8 + hh;
                float4 v;
                v.x = __uint_as_float(d[hh * 4 + 0]) + bias[0 * H_ + hcol];
                v.y = __uint_as_float(d[hh * 4 + 1]) + bias[1 * H_ + hcol];
                v.z = __uint_as_float(d[hh * 4 + 2]) + bias[2 * H_ + hcol];
                v.w = __uint_as_float(d[hh * 4 + 3]) + bias[3 * H_ + hcol];
                *(float4*)(dst + cg * 32 + hh * 4) = v;
            }
        }
    }
    __syncthreads();
    if (tid == 0)
        asm volatile("mbarrier.inval.shared.b64 [%0];" :: "r"(mbar) : "memory");
    if (wid == 0)
        asm volatile("tcgen05.dealloc.cta_group::1.sync.aligned.b32 %0, %1;"
                     :: "r"(tmem), "r"(512u));
#else
    const __nv_bfloat16* Ah = g_Ehi + (size_t)token * EP_;
    const __nv_bfloat16* Al = g_Elo + (size_t)token * EP_;
    float* dst = g_XZ + (size_t)(m0 + tid) * N4H;
    for (int n = bx * 512; n < bx * 512 + 512; n++) {
        float acc = 0.f;
        for (int k = 0; k < EP_; k++) {
            float a = __bfloat162float(Ah[k]) + __bfloat162float(Al[k]);
            size_t bi = (size_t)n * EP_ + k;
            float b = __bfloat162float(g_WxThi[bi]) + __bfloat162float(g_WxTlo[bi]);
            acc = fmaf(a, b, acc);
        }
        dst[n] = acc + bias[(n & 3) * H_ + (n >> 2)];
    }
#endif
}

// ---------------------------------------------------------------------------
// PERSISTENT fused LSTM (sorted rows): grid (16 N-tiles, 8 M-tiles).
// Each 16-CTA row group runs t < tilemax[group] and syncs via the R5-proven
// flag barrier (st.release absolute values; threads 0..15 acquire-poll the
// group's 16 flags). C/H in registers; final h written via perm.
// ---------------------------------------------------------------------------
__global__ __launch_bounds__(128)
void lstm_persist_kernel(const int* __restrict__ sl1, const int* __restrict__ sl2)
{
    const int tid = threadIdx.x;
    const int n0 = blockIdx.x * 128;
    const int m0 = blockIdx.y * 128;
    const int grp = blockIdx.y;
    const int cta = grp * GRP_ + blockIdx.x;
    const int tmax = g_tilemax[grp];

#if HAS_TC
    extern __shared__ char smem[];
    const int wid = tid >> 5;
    const int lane = tid & 31;
    uint32_t smem_base = smem_u32(smem);
    uint32_t mbar = smem_base + 8;

    if (wid == 0) {
        asm volatile("tcgen05.alloc.cta_group::1.sync.aligned.shared::cta.b32 [%0], %1;"
                     :: "r"(smem_base), "r"(128u) : "memory");
        asm volatile("tcgen05.relinquish_alloc_permit.cta_group::1.sync.aligned;");
    }
    if (tid == 0)
        asm volatile("mbarrier.init.shared.b64 [%0], 1;" :: "r"(mbar) : "memory");
    __syncthreads();
    uint32_t tmem;
    asm volatile("ld.shared.b32 %0, [%1];" : "=r"(tmem) : "r"(smem_base));

    const int r = m0 + wid * 32 + lane;   // == m0 + tid (sorted row)
    const int sl = g_slsort[r];
    const int idx0 = r * H_ + blockIdx.x * 32;

    const __nv_bfloat16* AhB[2] = { g_Hhi[0] + (size_t)(m0 + tid) * KH_,
                                    g_Hhi[1] + (size_t)(m0 + tid) * KH_ };
    const __nv_bfloat16* AlB[2] = { g_Hlo[0] + (size_t)(m0 + tid) * KH_,
                                    g_Hlo[1] + (size_t)(m0 + tid) * KH_ };
    const __nv_bfloat16* Bh = g_WhThi + (size_t)(n0 + tid) * KH_;
    const __nv_bfloat16* Bl = g_WhTlo + (size_t)(n0 + tid) * KH_;

    float c[32], h[32];
#pragma unroll
    for (int j = 0; j < 32; j++) { c[j] = 0.f; h[j] = 0.f; }

    for (int t = 0; t < tmax; t++) {
        const int rb = t & 1, wb = (t + 1) & 1;

        run_pipeline8(smem_base, tmem, mbar, tid, wid, AhB[rb], AlB[rb], Bh, Bl);

        const bool valid = (t < sl);
        const float* xz = g_XZ + ((size_t)t * R_ + r) * N4H + n0;

#pragma unroll
        for (int cg = 0; cg < 4; cg++) {
            float4 xv[8];
#pragma unroll
            for (int hh = 0; hh < 8; hh++)
                xv[hh] = *(const float4*)(xz + cg * 32 + hh * 4);
            uint32_t d[32];
            LDTM_X32(d, tmem + cg * 32);
            asm volatile("tcgen05.wait::ld.sync.aligned;" ::: "memory");
#pragma unroll
            for (int hh = 0; hh < 8; hh++) {
                int j = cg * 8 + hh;
                float zi = __uint_as_float(d[hh * 4 + 0]) + xv[hh].x;
                float zj = __uint_as_float(d[hh * 4 + 1]) + xv[hh].y;
                float zf = __uint_as_float(d[hh * 4 + 2]) + xv[hh].z;
                float zo = __uint_as_float(d[hh * 4 + 3]) + xv[hh].w;
                float nc = c[j] * sigmoidf_(zf + 1.f) + sigmoidf_(zi) * tanhf(zj);
                float nh = tanhf(nc) * sigmoidf_(zo);
                if (valid) { c[j] = nc; h[j] = nh; }
            }
        }
        asm volatile("tcgen05.fence::before_thread_sync;" ::: "memory");

        if (t + 1 < tmax) {
            // write H splits for next step's A tiles (read only by this group)
            uint32_t hi2[16], lo2[16];
#pragma unroll
            for (int j = 0; j < 16; j++) {
                float h0 = h[j * 2], h1 = h[j * 2 + 1];
                __nv_bfloat16 b0 = __float2bfloat16(h0);
                __nv_bfloat16 b1 = __float2bfloat16(h1);
                __nv_bfloat16 l0 = __float2bfloat16(h0 - __bfloat162float(b0));
                __nv_bfloat16 l1 = __float2bfloat16(h1 - __bfloat162float(b1));
                hi2[j] = (uint32_t)__bfloat16_as_ushort(b0) |
                         ((uint32_t)__bfloat16_as_ushort(b1) << 16);
                lo2[j] = (uint32_t)__bfloat16_as_ushort(l0) |
                         ((uint32_t)__bfloat16_as_ushort(l1) << 16);
            }
#pragma unroll
            for (int i = 0; i < 4; i++) {
                *(uint4*)(g_Hhi[wb] + idx0 + i * 8) = *(const uint4*)&hi2[i * 4];
                *(uint4*)(g_Hlo[wb] + idx0 + i * 8) = *(const uint4*)&lo2[i * 4];
            }

            // 16-CTA row-group barrier (R5-proven mechanism, group-scoped)
            __syncthreads();
            __threadfence();
            if (tid == 0) {
                asm volatile("st.release.gpu.global.s32 [%0], %1;"
                             :: "l"(&g_flags[cta]), "r"(t + 1) : "memory");
            }
            if (tid < GRP_) {
                int v;
                const int* fp = &g_flags[grp * GRP_ + tid];
                do {
                    asm volatile("ld.acquire.gpu.global.s32 %0, [%1];"
                                 : "=r"(v) : "l"(fp) : "memory");
                    if (v > t) break;
                    __nanosleep(64);
                } while (true);
            }
            __syncthreads();
        }
    }

    // publish final h at ORIGINAL row index
    {
        const int orig = g_perm[r];
        const int o0 = orig * H_ + blockIdx.x * 32;
#pragma unroll
        for (int i = 0; i < 8; i++)
            *(float4*)(g_H + o0 + i * 4) = *(const float4*)&h[i * 4];
    }

    __syncthreads();
    if (tid == 0)
        asm volatile("mbarrier.inval.shared.b64 [%0];" :: "r"(mbar) : "memory");
    if (wid == 0)
        asm volatile("tcgen05.dealloc.cta_group::1.sync.aligned.b32 %0, %1;"
                     :: "r"(tmem), "r"(128u));
#else
    // FFMA fallback (non-'a' gencode pass; never runs on GB300).
    const int r = m0 + tid;
    const int sl = g_slsort[r];
    const int hc0 = blockIdx.x * 32;
    float c[32], h[32];
    for (int j = 0; j < 32; j++) { c[j] = 0.f; h[j] = 0.f; }

    for (int t = 0; t < tmax; t++) {
        const int rb = t & 1, wb = (t + 1) & 1;
        const bool valid = (t < sl);
        const float* xz = g_XZ + ((size_t)t * R_ + r) * N4H;
        const __nv_bfloat16* Ah = g_Hhi[rb] + (size_t)r * KH_;
        const __nv_bfloat16* Al = g_Hlo[rb] + (size_t)r * KH_;

        for (int j = 0; j < 32; j++) {
            int n = (hc0 + j) * 4;
            float acc[4] = {0, 0, 0, 0};
            for (int k = 0; k < KH_; k++) {
                float a = __bfloat162float(Ah[k]) + __bfloat162float(Al[k]);
                for (int g = 0; g < 4; g++) {
                    size_t bi = (size_t)(n + g) * KH_ + k;
                    float bw = __bfloat162float(g_WhThi[bi]) + __bfloat162float(g_WhTlo[bi]);
                    acc[g] = fmaf(a, bw, acc[g]);
                }
            }
            float zi = acc[0] + xz[n + 0];
            float zj = acc[1] + xz[n + 1];
            float zf = acc[2] + xz[n + 2];
            float zo = acc[3] + xz[n + 3];
            float nc = c[j] * sigmoidf_(zf + 1.f) + sigmoidf_(zi) * tanhf(zj);
            float nh = tanhf(nc) * sigmoidf_(zo);
            if (valid) { c[j] = nc; h[j] = nh; }
        }
        if (t + 1 < tmax) {
            for (int j = 0; j < 32; j++) {
                int idx = r * H_ + hc0 + j;
                __nv_bfloat16 hb = __float2bfloat16(h[j]);
                g_Hhi[wb][idx] = hb;
                g_Hlo[wb][idx] = __float2bfloat16(h[j] - __bfloat162float(hb));
            }
            __syncthreads();
            __threadfence();
            if (tid == 0) atomicExch(&g_flags[cta], t + 1);
            if (tid < GRP_) {
                volatile int* fp = (volatile int*)&g_flags[grp * GRP_ + tid];
                while (*fp <= t) { __nanosleep(64); }
            }
            __threadfence();
            __syncthreads();
        }
    }
    const int orig = g_perm[r];
    for (int j = 0; j < 32; j++) g_H[orig * H_ + hc0 + j] = h[j];
#endif
}

// ---------------------------------------------------------------------------
// head (not a bottleneck)
// ---------------------------------------------------------------------------
__global__ __launch_bounds__(256)
void head_kernel(const int* __restrict__ sl1, const int* __restrict__ sl2,
                 const float* __restrict__ W1, const float* __restrict__ b1,
                 const float* __restrict__ W2, const float* __restrict__ b2,
                 float* __restrict__ out)
{
    __shared__ float hcs[4][2053];
    __shared__ float e1s[4][256];
    __shared__ float red[256];

    const int tid = threadIdx.x;
    const int b0  = blockIdx.x * 4;

    for (int rr = 0; rr < 4; rr++) {
        int bb = b0 + rr;
        const float* h1 = g_H + (size_t)bb * H_;
        const float* h2 = g_H + (size_t)(512 + bb) * H_;
        for (int k = tid; k < H_; k += 256) {
            float a = h1[k], c = h2[k];
            hcs[rr][k]        = a;
            hcs[rr][513 + k]  = c;
            hcs[rr][1026 + k] = a - c;
            hcs[rr][1540 + k] = a * c;
        }
        if (tid == 0) {
            float l1 = (float)sl1[bb] / (float)T_;
            float l2 = (float)sl2[bb] / (float)T_;
            hcs[rr][512]  = l1;
            hcs[rr][1025] = l2;
            hcs[rr][1538] = l1 - l2;
            hcs[rr][2052] = l1 * l2;
        }
    }
    __syncthreads();

    for (int rr = 0; rr < 4; rr++) {
        float v = 0.f;
        for (int k = tid; k < 513; k += 256) {
            float s = hcs[rr][1026 + k];
            v += s * s;
        }
        red[tid] = v;
        __syncthreads();
        for (int s = 128; s > 0; s >>= 1) {
            if (tid < s) red[tid] += red[tid + s];
            __syncthreads();
        }
        if (tid == 0) hcs[rr][1539] = red[0];
        __syncthreads();
    }

    float a0 = b1[tid], a1 = b1[tid], a2 = b1[tid], a3 = b1[tid];
    for (int k = 0; k < 2053; k++) {
        float w = W1[(size_t)k * M_ + tid];
        a0 = fmaf(hcs[0][k], w, a0);
        a1 = fmaf(hcs[1][k], w, a1);
        a2 = fmaf(hcs[2][k], w, a2);
        a3 = fmaf(hcs[3][k], w, a3);
    }
    e1s[0][tid] = fmaxf(a0, 0.f);
    e1s[1][tid] = fmaxf(a1, 0.f);
    e1s[2][tid] = fmaxf(a2, 0.f);
    e1s[3][tid] = fmaxf(a3, 0.f);
    __syncthreads();

    int wid  = tid >> 5;
    int lane = tid & 31;
    int rr   = wid >> 1;
    int j    = wid & 1;
    float s = 0.f;
    for (int k = lane; k < M_; k += 32)
        s = fmaf(e1s[rr][k], W2[k * 2 + j], s);
#pragma unroll
    for (int off = 16; off > 0; off >>= 1)
        s += __shfl_down_sync(0xffffffffu, s, off);
    if (lane == 0)
        out[(size_t)(b0 + rr) * 2 + j] = s + b2[j];
}

// ---------------------------------------------------------------------------
// launch
// ---------------------------------------------------------------------------
extern "C" void kernel_launch(void* const* d_in, const int* in_sizes, int n_in,
                              void* d_out, int out_size)
{
    const int*   input1  = (const int*)  d_in[0];
    const int*   input2  = (const int*)  d_in[1];
    const int*   seqlen1 = (const int*)  d_in[2];
    const int*   seqlen2 = (const int*)  d_in[3];
    const float* emb     = (const float*)d_in[4];
    const float* kern    = (const float*)d_in[5];
    const float* bias    = (const float*)d_in[6];
    const float* W1      = (const float*)d_in[7];
    const float* b1      = (const float*)d_in[8];
    const float* W2      = (const float*)d_in[9];
    const float* b2      = (const float*)d_in[10];
    float*       out     = (float*)d_out;

    cudaFuncSetAttribute(xproj_kernel, cudaFuncAttributeMaxDynamicSharedMemorySize, SMEM_BYTES);
    cudaFuncSetAttribute(lstm_persist_kernel, cudaFuncAttributeMaxDynamicSharedMemorySize, SMEM_BYTES);

    sort_kernel<<<1, 512>>>(seqlen1, seqlen2);
    init_state_kernel<<<(R_ * H_ + 255) / 256, 256>>>();
    split_emb_kernel<<<(int)(((size_t)V_ * EP_ + 255) / 256), 256>>>(emb);
    split_wx_kernel<<<(N4H * EP_ + 255) / 256, 256>>>(kern);
    split_wh_kernel<<<(N4H * KH_ + 255) / 256, 256>>>(kern);
    xproj_kernel<<<dim3(4, (T_ * R_) / 128), 128, SMEM_BYTES>>>(input1, input2, bias);
    lstm_persist_kernel<<<dim3(16, 8), 128, SMEM_BYTES>>>(seqlen1, seqlen2);
    head_kernel<<<B_ / 4, 256>>>(seqlen1, seqlen2, W1, b1, W2, b2, out);
}